// round 11
// baseline (speedup 1.0000x reference)
#include <cuda_runtime.h>
#include <math.h>

#define BB 32
#define SS 512
#define HH 768
#define WE 150
#define LL 9
#define NPOS (BB*SS)            // 16384
#define NSPANS (BB*4096)        // 131072
#define T_STRIDE 304            // [0:150]=start part, [152:302]=end part
#define WD_STRIDE 152
#define RANKCAP 32
#define KEYS_PER_B (RANKCAP*RANKCAP*9)   // 9216
#define NKEYS (BB*KEYS_PER_B)            // 294912
#define TROWS 8
#define KCH 24
#define NB 148
#define TPB 320
#define UT 64

typedef unsigned long long ull;

// static scratch; zero-initialized at load; pipeline restores entry state each call.
__device__ float    g_T[NPOS*T_STRIDE];
__device__ float    g_WD[16*WD_STRIDE];
__device__ float    g_ULOG[(size_t)NSPANS*12];
__device__ int      g_used[NPOS];       // cleared by compact phase after read
__device__ int      g_list[NPOS];
__device__ int      g_slotOfPos[NPOS];
__device__ int      g_rank[NPOS];
__device__ int      g_bcount[BB];       // reset in scatter phase
__device__ int      g_count;            // reset in scatter phase
__device__ int      g_ckey[NKEYS];      // 0=empty, owner=i+1; cleared in scatter phase
__device__ int      g_uslot[NKEYS];
__device__ int      g_key[NSPANS];
__device__ int      g_spanslot[NSPANS];
__device__ unsigned g_uinfo[NSPANS];
__device__ int      g_ucount;           // reset in scatter phase
__device__ int      g_tile;             // uniq work-steal; reset in scatter phase
__device__ int      g_tk;               // tgemm work-steal; reset in scatter phase
__device__ unsigned g_bar;              // grid barrier; reset by last arriver

__device__ __forceinline__ int clampi(int v, int lo, int hi) { return min(max(v, lo), hi); }

__device__ __forceinline__ ull ffma2(ull a, ull b, ull c) {
    ull d;
    asm("fma.rn.f32x2 %0, %1, %2, %3;" : "=l"(d) : "l"(a), "l"(b), "l"(c));
    return d;
}
__device__ __forceinline__ ull pack2(float x) {
    ull d;
    asm("mov.b64 %0, {%1, %1};" : "=l"(d) : "f"(x));
    return d;
}
__device__ __forceinline__ void unpack2(ull v, float& lo, float& hi) {
    asm("mov.b64 {%0, %1}, %2;" : "=f"(lo), "=f"(hi) : "l"(v));
}

// software grid barrier: all NB blocks are co-resident (1 CTA/SM by smem).
__device__ __forceinline__ void gridbar(unsigned target) {
    __threadfence();
    __syncthreads();
    if (threadIdx.x == 0) {
        atomicAdd(&g_bar, 1u);
        while (atomicAdd(&g_bar, 0u) < target) { }
    }
    __syncthreads();
}

// smem layout (floats):
// uniq region:
#define O_W2   0        // [150][160]
#define O_U    24000    // [152][64] h1T / [64][164] h2
#define O_W3   34496    // [150][12]
#define O_B2   36296    // [160]
#define O_B3   36456    // [12]
#define O_INFO 36468    // [64] unsigned
// tgemm region:
#define O_TG   36544
#define O_TW   (O_TG)            // [2][KCH][304]
#define O_TA   (O_TG + 14592)    // [192][8]
#define O_TROW (O_TG + 16128)    // [8] ints
#define O_TRED (O_TG + 16136)    // [160]
#define SMEM_FLOATS (O_TG + 16296)   // 52840 floats = 211360 B

__global__ void __launch_bounds__(TPB, 1)
k_fused(const float* __restrict__ seq,  const float* __restrict__ wt,
        const float* __restrict__ W1,   const float* __restrict__ b1,
        const float* __restrict__ W2,   const float* __restrict__ b2,
        const float* __restrict__ W3,   const float* __restrict__ b3,
        const int* __restrict__ spans,  const int* __restrict__ mask,
        const int* __restrict__ label,  float* __restrict__ out)
{
    extern __shared__ float sm[];
    float* sW2 = sm + O_W2;
    float* sU  = sm + O_U;
    float* sW3 = sm + O_W3;
    float* sB2 = sm + O_B2;
    float* sB3 = sm + O_B3;
    unsigned* sInfo = (unsigned*)(sm + O_INFO);
    float* sW  = sm + O_TW;
    float* sA  = sm + O_TA;
    int*  sRow = (int*)(sm + O_TROW);
    float* sRed = sm + O_TRED;
    __shared__ float sL;
    __shared__ int sTile;

    int tid = threadIdx.x;
    int bid = blockIdx.x;
    float* loss_ptr = out + (size_t)NSPANS * LL;

    // ---- preload W2/W3/b2/b3 into smem (overlaps early phases) ----
    for (int idx = tid; idx < 150*160; idx += TPB) {
        int k = idx / 160, j = idx - k*160;
        sW2[idx] = (j < 150) ? W2[k*150 + j] : 0.f;
    }
    for (int idx = tid; idx < 150*12; idx += TPB) {
        int k = idx / 12, l = idx - k*12;
        sW3[idx] = (l < 9) ? W3[k*9 + l] : 0.f;
    }
    if (tid < 160) sB2[tid] = (tid < 150) ? b2[tid] : 0.f;
    if (tid >= 160 && tid < 172) sB3[tid - 160] = (tid - 160 < 9) ? b3[tid - 160] : 0.f;
    if (bid == 0 && tid == 0) *loss_ptr = 0.f;

    // ---- P0: mark used positions ----
    for (int i = bid * TPB + tid; i < NSPANS; i += NB * TPB) {
        int b = i >> 12;
        int s = clampi(spans[3*i], 0, SS-1);
        int e = clampi(spans[3*i + 1], 0, SS-1);
        g_used[(b << 9) + s] = 1;
        g_used[(b << 9) + e] = 1;
    }
    gridbar(1u * NB);

    // ---- P1: compact (self-clearing g_used) ----
    for (int i = bid * TPB + tid; i < NPOS; i += NB * TPB) {
        if (g_used[i]) {
            int slot = atomicAdd(&g_count, 1);
            g_list[slot] = i;
            g_slotOfPos[i] = slot;
            g_rank[i] = atomicAdd(&g_bcount[i >> 9], 1);
            g_used[i] = 0;
        }
    }
    gridbar(2u * NB);

    int cnt = *(volatile const int*)&g_count;

    // ---- P2: claim + zero g_T rows ----
    for (int i = bid * TPB + tid; i < NSPANS; i += NB * TPB) {
        int b = i >> 12;
        int si = clampi(spans[3*i], 0, SS-1);
        int ei = clampi(spans[3*i + 1], 0, SS-1);
        int wi = clampi(spans[3*i + 2], 0, 8);
        int rs = g_rank[(b << 9) + si];
        int re = g_rank[(b << 9) + ei];
        int key = -2;
        bool own;
        if (rs < RANKCAP && re < RANKCAP) {
            key = b * KEYS_PER_B + (rs * RANKCAP + re) * 9 + wi;
            own = (atomicCAS(&g_ckey[key], 0, i + 1) == 0);
        } else {
            own = true;
        }
        g_key[i] = key;
        if (own) {
            int ss = g_slotOfPos[(b << 9) + si];
            int se = g_slotOfPos[(b << 9) + ei];
            int slot = atomicAdd(&g_ucount, 1);
            g_uinfo[slot] = (unsigned)ss | ((unsigned)se << 14) | ((unsigned)wi << 28);
            if (key >= 0) g_uslot[key] = slot;
            else g_spanslot[i] = slot;
        }
    }
    {
        int nz4 = cnt * (T_STRIDE / 4);
        float4 z = make_float4(0.f, 0.f, 0.f, 0.f);
        float4* tz = (float4*)g_T;
        for (int i = bid * TPB + tid; i < nz4; i += NB * TPB) tz[i] = z;
    }
    gridbar(3u * NB);

    // ---- P3: T projection GEMM + WD, work-stealing tasks ----
    // NOTE: every __syncthreads() in this phase is at full-block scope
    // (never under a tid< guard) — intra-warp divergent bar.sync hangs.
    {
        int nrt = (cnt + TROWS - 1) / TROWS;
        int ngemm = nrt * 4;
        int ntasks = ngemm + 9;
        int cp = (tid < 300) ? (tid % 150) : 0;
        int rg = (tid < 300) ? (tid / 150) : 0;
        int jj = 2 * cp;
        int col0 = (jj < 150) ? jj : (jj + 2);

        for (;;) {
            if (tid == 0) sTile = atomicAdd(&g_tk, 1);
            __syncthreads();
            int task = sTile;
            if (task >= ntasks) break;

            if (task < ngemm) {
                int rt = task >> 2, ks = task & 3;
                int r0 = rt * TROWS, k0 = ks * 192;

                if (tid < TROWS) sRow[tid] = g_list[min(r0 + tid, cnt - 1)];
                __syncthreads();

                for (int idx = tid; idx < 192 * TROWS; idx += TPB) {
                    int k = idx >> 3, r = idx & 7;
                    sA[idx] = fmaxf(seq[(size_t)sRow[r] * HH + k0 + k], 0.f);
                }
                if (tid < 300) {
                    const float* src = (tid < 150)
                        ? (W1 + (size_t)k0 * WE + tid)
                        : (W1 + (size_t)(HH + k0) * WE + (tid - 150));
                    #pragma unroll
                    for (int kk = 0; kk < KCH; kk++)
                        sW[kk * 304 + tid] = src[(size_t)kk * WE];
                }
                __syncthreads();

                ull acc00 = 0ull, acc01 = 0ull, acc10 = 0ull, acc11 = 0ull;

                #pragma unroll 1
                for (int c = 0; c < 8; c++) {
                    if (c + 1 < 8 && tid < 300) {
                        int kb = k0 + (c + 1) * KCH;
                        const float* src = (tid < 150)
                            ? (W1 + (size_t)kb * WE + tid)
                            : (W1 + (size_t)(HH + kb) * WE + (tid - 150));
                        float* dst = sW + ((c + 1) & 1) * KCH * 304;
                        #pragma unroll
                        for (int kk = 0; kk < KCH; kk++)
                            dst[kk * 304 + tid] = src[(size_t)kk * WE];
                    }
                    if (tid < 300) {
                        const float* wb = sW + (c & 1) * KCH * 304;
                        const float* ab = sA + c * KCH * TROWS + rg * 4;
                        #pragma unroll
                        for (int kk = 0; kk < KCH; kk++) {
                            ull wpair = *(const ull*)&wb[kk * 304 + jj];
                            float wx, wy;
                            unpack2(wpair, wx, wy);
                            ull b0 = pack2(wx), b1v = pack2(wy);
                            ull a0 = *(const ull*)&ab[kk * TROWS];
                            ull a1 = *(const ull*)&ab[kk * TROWS + 2];
                            acc00 = ffma2(a0, b0,  acc00);
                            acc01 = ffma2(a0, b1v, acc01);
                            acc10 = ffma2(a1, b0,  acc10);
                            acc11 = ffma2(a1, b1v, acc11);
                        }
                    }
                    __syncthreads();
                }

                if (tid < 300) {
                    int rbase = r0 + rg * 4;
                    ull accs[2][2] = {{acc00, acc01}, {acc10, acc11}};
                    #pragma unroll
                    for (int p = 0; p < 2; p++) {
                        int rA = rbase + 2 * p;
                        #pragma unroll
                        for (int cc = 0; cc < 2; cc++) {
                            float lo, hi;
                            unpack2(accs[p][cc], lo, hi);
                            if (rA < cnt)
                                atomicAdd(&g_T[(size_t)rA * T_STRIDE + col0 + cc], lo);
                            if (rA + 1 < cnt)
                                atomicAdd(&g_T[(size_t)(rA + 1) * T_STRIDE + col0 + cc], hi);
                        }
                    }
                }
                __syncthreads();
            } else {
                int w = task - ngemm;   // 0..8
                for (int t = tid; t < 150; t += TPB) sA[t] = fmaxf(wt[w*150 + t], 0.f);
                __syncthreads();
                int g = tid / 150;      // 0..1 for tid<300
                int j = tid - g * 150;
                float acc = 0.f;
                if (tid < 300) {
                    acc = (g == 0) ? b1[j] : 0.f;
                    int kst = g * 75;
                    #pragma unroll 8
                    for (int k = kst; k < kst + 75; k++)
                        acc = fmaf(sA[k], W1[(size_t)(2*HH + k) * WE + j], acc);
                    if (g == 1) sRed[j] = acc;
                }
                __syncthreads();   // full-block scope
                if (tid < 150)
                    g_WD[w * WD_STRIDE + j] = acc + sRed[j];
                __syncthreads();
            }
        }
    }
    gridbar(4u * NB);

    // ---- P4: unique rows -> h1 -> @W2+b2 (FFMA2) -> @W3+b3 -> g_ULOG ----
    {
        int nu = *(volatile const int*)&g_ucount;
        int r0 = (tid & 15) * 4;
        int c0 = (tid >> 4) * 10;

        for (;;) {
            if (tid == 0) sTile = atomicAdd(&g_tile, 1);
            __syncthreads();
            int base = sTile * UT;
            if (base >= nu) break;

            if (tid < UT)
                sInfo[tid] = (base + tid < nu) ? g_uinfo[base + tid] : 0u;
            __syncthreads();

            for (int idx = tid; idx < 38*64; idx += TPB) {
                int kq = idx >> 6, r = idx & 63;
                unsigned info = sInfo[r];
                int ss = info & 0x3FFF, se = (info >> 14) & 0x3FFF, w = info >> 28;
                float4 ts = *(const float4*)&g_T[(size_t)ss*T_STRIDE + kq*4];
                float4 te = *(const float4*)&g_T[(size_t)se*T_STRIDE + 152 + kq*4];
                float4 wd = *(const float4*)&g_WD[w*WD_STRIDE + kq*4];
                sU[(kq*4 + 0)*64 + r] = fmaxf(ts.x + te.x + wd.x, 0.f);
                sU[(kq*4 + 1)*64 + r] = fmaxf(ts.y + te.y + wd.y, 0.f);
                sU[(kq*4 + 2)*64 + r] = fmaxf(ts.z + te.z + wd.z, 0.f);
                sU[(kq*4 + 3)*64 + r] = fmaxf(ts.w + te.w + wd.w, 0.f);
            }
            __syncthreads();

            ull acc[4][5];
            if (tid < 256) {
                const ull* bp = (const ull*)&sB2[c0];
                #pragma unroll
                for (int p = 0; p < 5; p++) {
                    ull bv = bp[p];
                    #pragma unroll
                    for (int ri = 0; ri < 4; ri++) acc[ri][p] = bv;
                }
                #pragma unroll 2
                for (int k = 0; k < 150; k++) {
                    float4 a = *(const float4*)&sU[k*64 + r0];
                    ull ap[4] = {pack2(a.x), pack2(a.y), pack2(a.z), pack2(a.w)};
                    const ull* bw = (const ull*)&sW2[k*160 + c0];
                    ull bv[5] = {bw[0], bw[1], bw[2], bw[3], bw[4]};
                    #pragma unroll
                    for (int ri = 0; ri < 4; ri++)
                        #pragma unroll
                        for (int p = 0; p < 5; p++)
                            acc[ri][p] = ffma2(ap[ri], bv[p], acc[ri][p]);
                }
            }
            __syncthreads();   // all h1 reads done before overwriting sU

            if (tid < 256) {
                #pragma unroll
                for (int ri = 0; ri < 4; ri++)
                    #pragma unroll
                    for (int p = 0; p < 5; p++)
                        *(ull*)&sU[(r0 + ri)*164 + c0 + 2*p] = acc[ri][p];
            }
            __syncthreads();

            for (int idx = tid; idx < UT*LL; idx += TPB) {
                int r = idx / LL, l = idx - r*LL;
                float a = sB3[l];
                #pragma unroll 5
                for (int k = 0; k < 150; k++)
                    a = fmaf(sU[r*164 + k], sW3[k*12 + l], a);
                if (base + r < nu)
                    g_ULOG[(size_t)(base + r)*12 + l] = a;
            }
            __syncthreads();
        }
    }
    gridbar(5u * NB);

    // ---- P5: scatter logits + NLL loss + reset state ----
    if (tid == 0) sL = 0.f;
    __syncthreads();
    {
        float contrib = 0.f;
        for (int i = bid * TPB + tid; i < NSPANS; i += NB * TPB) {
            int key = g_key[i];
            int slot;
            if (key >= 0) { slot = g_uslot[key]; g_ckey[key] = 0; }
            else          { slot = g_spanslot[i]; }
            const float* Lr = &g_ULOG[(size_t)slot * 12];
            float4 p0 = *(const float4*)Lr;
            float4 p1 = *(const float4*)(Lr + 4);
            float l8 = Lr[8];
            float L[9] = {p0.x, p0.y, p0.z, p0.w, p1.x, p1.y, p1.z, p1.w, l8};
            float* o = out + (size_t)i * LL;
            #pragma unroll
            for (int l = 0; l < LL; l++) o[l] = L[l];
            if (mask[i] == 1) {
                float m = L[0];
                #pragma unroll
                for (int l = 1; l < LL; l++) m = fmaxf(m, L[l]);
                float ssum = 0.f;
                #pragma unroll
                for (int l = 0; l < LL; l++) ssum += expf(L[l] - m);
                int lb = clampi(label[i], 0, LL-1);
                contrib += (m + logf(ssum)) - L[lb];
            }
        }
        atomicAdd(&sL, contrib);
    }
    __syncthreads();
    if (tid == 0 && sL != 0.f) atomicAdd(loss_ptr, sL);
    if (bid == 0 && tid == 0) {
        g_count = 0; g_ucount = 0; g_tile = 0; g_tk = 0;
        #pragma unroll
        for (int w = 0; w < BB; w++) g_bcount[w] = 0;
    }

    // final arrive: last arriver resets the barrier counter (no spin)
    __threadfence();
    __syncthreads();
    if (tid == 0) {
        unsigned v = atomicAdd(&g_bar, 1u) + 1u;
        if (v == 6u * NB) g_bar = 0u;
    }
}

extern "C" void kernel_launch(void* const* d_in, const int* in_sizes, int n_in,
                              void* d_out, int out_size) {
    const float* seq = (const float*)d_in[0];
    const float* wt  = (const float*)d_in[1];
    const float* W1  = (const float*)d_in[2];
    const float* b1  = (const float*)d_in[3];
    const float* W2  = (const float*)d_in[4];
    const float* b2  = (const float*)d_in[5];
    const float* W3  = (const float*)d_in[6];
    const float* b3  = (const float*)d_in[7];
    const int* spans = (const int*)d_in[8];
    const int* smask = (const int*)d_in[9];
    const int* slab  = (const int*)d_in[10];
    float* out = (float*)d_out;

    static const size_t SMEM = (size_t)SMEM_FLOATS * 4;   // 211360 B
    cudaFuncSetAttribute(k_fused, cudaFuncAttributeMaxDynamicSharedMemorySize, (int)SMEM);
    k_fused<<<NB, TPB, SMEM>>>(seq, wt, W1, b1, W2, b2, W3, b3,
                               spans, smask, slab, out);
}

// round 12
// speedup vs baseline: 1.0622x; 1.0622x over previous
#include <cuda_runtime.h>
#include <math.h>

#define BB 32
#define SS 512
#define HH 768
#define WE 150
#define LL 9
#define NPOS (BB*SS)            // 16384
#define NSPANS (BB*4096)        // 131072
#define T_STRIDE 304            // [0:150]=start part, [152:302]=end part
#define WD_STRIDE 152
#define RANKCAP 32
#define KEYS_PER_B (RANKCAP*RANKCAP*9)   // 9216
#define NKEYS (BB*KEYS_PER_B)            // 294912
#define TROWS 8
#define KCH 24
#define KSP 8                    // k split: 8 tasks x 96
#define UT 64

typedef unsigned long long ull;

// static scratch; zero-initialized at load; pipeline restores entry state each call.
__device__ float    g_T[NPOS*T_STRIDE];
__device__ float    g_WD[16*WD_STRIDE];
__device__ float    g_ULOG[(size_t)NSPANS*12];   // [0:9)=logits, [9]=lse
__device__ int      g_used[NPOS];       // cleared by k_compact after read
__device__ int      g_list[NPOS];
__device__ int      g_slotOfPos[NPOS];
__device__ int      g_rank[NPOS];
__device__ int      g_bcount[BB];       // reset by k_scatter
__device__ int      g_count;            // reset by k_scatter
__device__ int      g_ckey[NKEYS];      // 0=empty, owner=i+1; cleared by k_scatter
__device__ int      g_uslot[NKEYS];
__device__ int      g_key[NSPANS];
__device__ int      g_spanslot[NSPANS];
__device__ unsigned g_uinfo[NSPANS];
__device__ int      g_ucount;           // reset by k_scatter
__device__ int      g_tile;             // uniq work-steal; reset by k_scatter

__device__ __forceinline__ int clampi(int v, int lo, int hi) { return min(max(v, lo), hi); }

__device__ __forceinline__ ull ffma2(ull a, ull b, ull c) {
    ull d;
    asm("fma.rn.f32x2 %0, %1, %2, %3;" : "=l"(d) : "l"(a), "l"(b), "l"(c));
    return d;
}
__device__ __forceinline__ ull pack2(float x) {
    ull d;
    asm("mov.b64 %0, {%1, %1};" : "=l"(d) : "f"(x));
    return d;
}
__device__ __forceinline__ void unpack2(ull v, float& lo, float& hi) {
    asm("mov.b64 {%0, %1}, %2;" : "=f"(lo), "=f"(hi) : "l"(v));
}

// K1: mark used positions + zero loss
__global__ void k_mark(const int* __restrict__ spans, float* __restrict__ loss_ptr) {
    int i = blockIdx.x * blockDim.x + threadIdx.x;
    if (i == 0) *loss_ptr = 0.f;
    if (i >= NSPANS) return;
    int b = i >> 12;
    int s = clampi(spans[3*i], 0, SS-1);
    int e = clampi(spans[3*i + 1], 0, SS-1);
    g_used[(b << 9) + s] = 1;
    g_used[(b << 9) + e] = 1;
}

// K2: compact used positions (and self-clear g_used)
__global__ void k_compact() {
    int i = blockIdx.x * blockDim.x + threadIdx.x;
    if (i >= NPOS) return;
    if (g_used[i]) {
        int slot = atomicAdd(&g_count, 1);
        g_list[slot] = i;
        g_slotOfPos[i] = slot;
        g_rank[i] = atomicAdd(&g_bcount[i >> 9], 1);
        g_used[i] = 0;
    }
}

// K3: blocks [0,512): claim; blocks [512,544): zero g_T rows
__global__ void k_claim(const int* __restrict__ spans) {
    int bi = blockIdx.x;
    int tid = threadIdx.x;
    if (bi < 512) {
        int i = bi * 256 + tid;
        int b = i >> 12;
        int si = clampi(spans[3*i], 0, SS-1);
        int ei = clampi(spans[3*i + 1], 0, SS-1);
        int wi = clampi(spans[3*i + 2], 0, 8);
        int rs = g_rank[(b << 9) + si];
        int re = g_rank[(b << 9) + ei];
        int key = -2;
        bool own;
        if (rs < RANKCAP && re < RANKCAP) {
            key = b * KEYS_PER_B + (rs * RANKCAP + re) * 9 + wi;
            own = (atomicCAS(&g_ckey[key], 0, i + 1) == 0);
        } else {
            own = true;
        }
        g_key[i] = key;
        if (own) {
            int ss = g_slotOfPos[(b << 9) + si];
            int se = g_slotOfPos[(b << 9) + ei];
            int slot = atomicAdd(&g_ucount, 1);
            g_uinfo[slot] = (unsigned)ss | ((unsigned)se << 14) | ((unsigned)wi << 28);
            if (key >= 0) g_uslot[key] = slot;
            else g_spanslot[i] = slot;
        }
    } else {
        int cnt = g_count;
        for (int slot = bi - 512; slot < cnt; slot += 32) {
            float4* tz = (float4*)(g_T + (size_t)slot * T_STRIDE);
            for (int t = tid; t < T_STRIDE/4; t += 256)
                tz[t] = make_float4(0.f, 0.f, 0.f, 0.f);
        }
    }
}

// K4: T projection. Tasks: (rowtile of 8) x (ksplit of 8, k=96 each).
// smem ~62 KB -> 2 CTAs/SM co-resident hide latency.
__global__ void __launch_bounds__(300, 2)
k_TgemmWD(const float* __restrict__ seq, const float* __restrict__ W1,
          const float* __restrict__ wt, const float* __restrict__ b1) {
    extern __shared__ float smem[];
    float* sW  = smem;                      // [2][KCH][304]
    float* sA  = smem + 2*KCH*304;          // [96][8] k-major
    int*  sRow = (int*)(sA + 96*TROWS);     // [8]
    float* sRed = (float*)(sRow + 8);       // [160]

    int cnt = g_count;
    int nrt = (cnt + TROWS - 1) / TROWS;
    int ngemm = nrt * KSP;
    int ntasks = ngemm + 9;
    int tid = threadIdx.x;
    int cp = tid % 150;
    int rg = tid / 150;                     // 0..1 -> rows rg*4..rg*4+3
    int jj = 2 * cp;
    int col0 = (jj < 150) ? jj : (jj + 2);

    for (int task = blockIdx.x; task < ntasks; task += gridDim.x) {
        if (task < ngemm) {
            int rt = task >> 3, ks = task & 7;
            int r0 = rt * TROWS, k0 = ks * 96;

            if (tid < TROWS) sRow[tid] = g_list[min(r0 + tid, cnt - 1)];
            __syncthreads();

            for (int idx = tid; idx < 96 * TROWS; idx += 300) {
                int k = idx >> 3, r = idx & 7;
                sA[idx] = fmaxf(seq[(size_t)sRow[r] * HH + k0 + k], 0.f);
            }
            {
                const float* src = (tid < 150)
                    ? (W1 + (size_t)k0 * WE + tid)
                    : (W1 + (size_t)(HH + k0) * WE + (tid - 150));
                #pragma unroll
                for (int kk = 0; kk < KCH; kk++)
                    sW[kk * 304 + tid] = src[(size_t)kk * WE];
            }
            __syncthreads();

            ull acc00 = 0ull, acc01 = 0ull, acc10 = 0ull, acc11 = 0ull;

            #pragma unroll 1
            for (int c = 0; c < 4; c++) {
                if (c + 1 < 4) {
                    int kb = k0 + (c + 1) * KCH;
                    const float* src = (tid < 150)
                        ? (W1 + (size_t)kb * WE + tid)
                        : (W1 + (size_t)(HH + kb) * WE + (tid - 150));
                    float* dst = sW + ((c + 1) & 1) * KCH * 304;
                    #pragma unroll
                    for (int kk = 0; kk < KCH; kk++)
                        dst[kk * 304 + tid] = src[(size_t)kk * WE];
                }
                {
                    const float* wb = sW + (c & 1) * KCH * 304;
                    const float* ab = sA + c * KCH * TROWS + rg * 4;
                    #pragma unroll
                    for (int kk = 0; kk < KCH; kk++) {
                        ull wpair = *(const ull*)&wb[kk * 304 + jj];
                        float wx, wy;
                        unpack2(wpair, wx, wy);
                        ull b0 = pack2(wx), b1v = pack2(wy);
                        ull a0 = *(const ull*)&ab[kk * TROWS];
                        ull a1 = *(const ull*)&ab[kk * TROWS + 2];
                        acc00 = ffma2(a0, b0,  acc00);
                        acc01 = ffma2(a0, b1v, acc01);
                        acc10 = ffma2(a1, b0,  acc10);
                        acc11 = ffma2(a1, b1v, acc11);
                    }
                }
                __syncthreads();
            }

            {
                int rbase = r0 + rg * 4;
                ull accs[2][2] = {{acc00, acc01}, {acc10, acc11}};
                #pragma unroll
                for (int p = 0; p < 2; p++) {
                    int rA = rbase + 2 * p;
                    #pragma unroll
                    for (int cc = 0; cc < 2; cc++) {
                        float lo, hi;
                        unpack2(accs[p][cc], lo, hi);
                        if (rA < cnt)
                            atomicAdd(&g_T[(size_t)rA * T_STRIDE + col0 + cc], lo);
                        if (rA + 1 < cnt)
                            atomicAdd(&g_T[(size_t)(rA + 1) * T_STRIDE + col0 + cc], hi);
                    }
                }
            }
            __syncthreads();
        } else {
            int w = task - ngemm;   // 0..8
            for (int t = tid; t < 150; t += 300) sA[t] = fmaxf(wt[w*150 + t], 0.f);
            __syncthreads();
            int g = tid / 150;      // 0..1
            int j = tid - g * 150;
            float acc = (g == 0) ? b1[j] : 0.f;
            int kst = g * 75;
            #pragma unroll 8
            for (int k = kst; k < kst + 75; k++)
                acc = fmaf(sA[k], W1[(size_t)(2*HH + k) * WE + j], acc);
            if (g == 1) sRed[j] = acc;
            __syncthreads();
            if (g == 0) g_WD[w * WD_STRIDE + j] = acc + sRed[j];
            __syncthreads();
        }
    }
}

// K5: unique rows -> h1 -> @W2+b2 (FFMA2) -> @W3+b3 -> logits + lse -> g_ULOG
__global__ void __launch_bounds__(256, 1)
k_uniq(const float* __restrict__ W2, const float* __restrict__ b2,
       const float* __restrict__ W3, const float* __restrict__ b3)
{
    extern __shared__ float sm[];
    float* sW2 = sm;                     // [150][160]
    float* sU  = sm + 24000;             // union: h1T [152][64] / h2 [64][164]
    float* sW3 = sm + 34496;             // [150][12]
    float* sB2 = sm + 36296;             // [160]
    float* sB3 = sm + 36456;             // [12]
    unsigned* sInfo = (unsigned*)(sm + 36468);  // [64]
    int* sTile = (int*)(sm + 36532);
    float* sLg = sm + 36536;             // [64][12] logits staging for lse
    int tid = threadIdx.x;

    for (int idx = tid; idx < 150*160; idx += 256) {
        int k = idx / 160, j = idx - k*160;
        sW2[idx] = (j < 150) ? W2[k*150 + j] : 0.f;
    }
    for (int idx = tid; idx < 150*12; idx += 256) {
        int k = idx / 12, l = idx - k*12;
        sW3[idx] = (l < 9) ? W3[k*9 + l] : 0.f;
    }
    if (tid < 160) sB2[tid] = (tid < 150) ? b2[tid] : 0.f;
    if (tid < 12)  sB3[tid] = (tid < 9)  ? b3[tid] : 0.f;

    int nu = g_ucount;
    int r0 = (tid & 15) * 4;     // 4 consecutive rows
    int c0 = (tid >> 4) * 10;    // 10 cols = 5 packed pairs

    for (;;) {
        if (tid == 0) *sTile = atomicAdd(&g_tile, 1);
        __syncthreads();
        int base = (*sTile) * UT;
        if (base >= nu) break;

        if (tid < UT)
            sInfo[tid] = (base + tid < nu) ? g_uinfo[base + tid] : 0u;
        __syncthreads();

        // gather h1, k-major [k][64], float4 over k
        for (int idx = tid; idx < 38*64; idx += 256) {
            int kq = idx >> 6, r = idx & 63;
            unsigned info = sInfo[r];
            int ss = info & 0x3FFF, se = (info >> 14) & 0x3FFF, w = info >> 28;
            float4 ts = *(const float4*)&g_T[(size_t)ss*T_STRIDE + kq*4];
            float4 te = *(const float4*)&g_T[(size_t)se*T_STRIDE + 152 + kq*4];
            float4 wd = *(const float4*)&g_WD[w*WD_STRIDE + kq*4];
            sU[(kq*4 + 0)*64 + r] = fmaxf(ts.x + te.x + wd.x, 0.f);
            sU[(kq*4 + 1)*64 + r] = fmaxf(ts.y + te.y + wd.y, 0.f);
            sU[(kq*4 + 2)*64 + r] = fmaxf(ts.z + te.z + wd.z, 0.f);
            sU[(kq*4 + 3)*64 + r] = fmaxf(ts.w + te.w + wd.w, 0.f);
        }
        __syncthreads();

        // h2 = h1 @ W2 + b2, packed column pairs (FFMA2)
        ull acc[4][5];
        {
            const ull* bp = (const ull*)&sB2[c0];
            #pragma unroll
            for (int p = 0; p < 5; p++) {
                ull bv = bp[p];
                #pragma unroll
                for (int ri = 0; ri < 4; ri++) acc[ri][p] = bv;
            }
        }
        #pragma unroll 2
        for (int k = 0; k < 150; k++) {
            float4 a = *(const float4*)&sU[k*64 + r0];
            ull ap[4] = {pack2(a.x), pack2(a.y), pack2(a.z), pack2(a.w)};
            const ull* bw = (const ull*)&sW2[k*160 + c0];
            ull bv[5] = {bw[0], bw[1], bw[2], bw[3], bw[4]};
            #pragma unroll
            for (int ri = 0; ri < 4; ri++)
                #pragma unroll
                for (int p = 0; p < 5; p++)
                    acc[ri][p] = ffma2(ap[ri], bv[p], acc[ri][p]);
        }
        __syncthreads();   // all h1 reads done before overwriting sU

        #pragma unroll
        for (int ri = 0; ri < 4; ri++)
            #pragma unroll
            for (int p = 0; p < 5; p++)
                *(ull*)&sU[(r0 + ri)*164 + c0 + 2*p] = acc[ri][p];
        __syncthreads();

        // logits = h2 @ W3 + b3 (also staged to sLg for lse)
        for (int idx = tid; idx < UT*LL; idx += 256) {
            int r = idx / LL, l = idx - r*LL;
            float a = sB3[l];
            #pragma unroll 5
            for (int k = 0; k < 150; k++)
                a = fmaf(sU[r*164 + k], sW3[k*12 + l], a);
            sLg[r*12 + l] = a;
            if (base + r < nu)
                g_ULOG[(size_t)(base + r)*12 + l] = a;
        }
        __syncthreads();

        // lse per unique row
        if (tid < UT && base + tid < nu) {
            float m = sLg[tid*12];
            #pragma unroll
            for (int l = 1; l < LL; l++) m = fmaxf(m, sLg[tid*12 + l]);
            float ssum = 0.f;
            #pragma unroll
            for (int l = 0; l < LL; l++) ssum += expf(sLg[tid*12 + l] - m);
            g_ULOG[(size_t)(base + tid)*12 + 9] = m + logf(ssum);
        }
        __syncthreads();
    }
}

// K6: scatter logits per span + NLL via precomputed lse + restore state
__global__ void k_scatter(const int* __restrict__ mask,
                          const int* __restrict__ label,
                          float* __restrict__ out)
{
    __shared__ float sL;
    if (threadIdx.x == 0) sL = 0.f;
    __syncthreads();
    int i = blockIdx.x * blockDim.x + threadIdx.x;
    float contrib = 0.f;
    if (i < NSPANS) {
        int key = g_key[i];
        int slot;
        if (key >= 0) { slot = g_uslot[key]; g_ckey[key] = 0; }
        else          { slot = g_spanslot[i]; }
        const float* Lr = &g_ULOG[(size_t)slot * 12];
        float4 p0 = *(const float4*)Lr;
        float4 p1 = *(const float4*)(Lr + 4);
        float2 p2 = *(const float2*)(Lr + 8);   // [8]=logit8, [9]=lse
        float L[9] = {p0.x, p0.y, p0.z, p0.w, p1.x, p1.y, p1.z, p1.w, p2.x};
        float* o = out + (size_t)i * LL;
        #pragma unroll
        for (int l = 0; l < LL; l++) o[l] = L[l];
        if (mask[i] == 1) {
            int lb = clampi(label[i], 0, LL-1);
            contrib = p2.y - L[lb];
        }
    }
    atomicAdd(&sL, contrib);
    __syncthreads();
    if (threadIdx.x == 0 && sL != 0.f)
        atomicAdd(&out[(size_t)NSPANS * LL], sL);
    if (blockIdx.x == 0 && threadIdx.x == 0) {
        g_count = 0; g_ucount = 0; g_tile = 0;
        #pragma unroll
        for (int w = 0; w < BB; w++) g_bcount[w] = 0;
    }
}

extern "C" void kernel_launch(void* const* d_in, const int* in_sizes, int n_in,
                              void* d_out, int out_size) {
    const float* seq = (const float*)d_in[0];
    const float* wt  = (const float*)d_in[1];
    const float* W1  = (const float*)d_in[2];
    const float* b1  = (const float*)d_in[3];
    const float* W2  = (const float*)d_in[4];
    const float* b2  = (const float*)d_in[5];
    const float* W3  = (const float*)d_in[6];
    const float* b3  = (const float*)d_in[7];
    const int* spans = (const int*)d_in[8];
    const int* smask = (const int*)d_in[9];
    const int* slab  = (const int*)d_in[10];
    float* out = (float*)d_out;

    static const size_t SMEM_UNIQ = (size_t)(36536 + 768) * 4;   // 149216 B
    static const size_t SMEM_TG   = (size_t)(2*KCH*304 + 96*TROWS + 8 + 160 + 8) * 4;
    cudaFuncSetAttribute(k_uniq, cudaFuncAttributeMaxDynamicSharedMemorySize, (int)SMEM_UNIQ);
    cudaFuncSetAttribute(k_TgemmWD, cudaFuncAttributeMaxDynamicSharedMemorySize, (int)SMEM_TG);

    k_mark<<<NSPANS/256, 256>>>(spans, out + (size_t)NSPANS * LL);
    k_compact<<<NPOS/256, 256>>>();
    k_claim<<<544, 256>>>(spans);
    k_TgemmWD<<<296, 300, SMEM_TG>>>(seq, W1, wt, b1);
    k_uniq<<<148, 256, SMEM_UNIQ>>>(W2, b2, W3, b3);
    k_scatter<<<NSPANS/256, 256>>>(smask, slab, out);
}